// round 2
// baseline (speedup 1.0000x reference)
#include <cuda_runtime.h>
#include <math.h>

#define Mr 32768
#define GDc 384
#define NFFT 16384
#define HALFN 8192
#define SCALE_U (1.0f / (16384.0f * 16384.0f))

// ---------------- scratch (device globals) ----------------
__device__ float  g_x   [(long long)Mr * GDc];          // emb @ W_proj [B,S,384]
__device__ float  g_zc  [(long long)Mr * GDc];          // conv out     [B,S,384]
__device__ float  g_t   [(long long)Mr * 128];          // rope(emb)
__device__ float  g_hmid[(long long)Mr * 128];          // gelu(LN(...))
__device__ float  g_hT  [(long long)4 * 2 * 128 * 8192];// h normalized [B,N,D,S]
__device__ float  g_vT  [(long long)4 * 128 * 8192];    // recurrence   [B,D,S]
__device__ float2 g_tw  [HALFN];                        // W_N^k

// ---------------- twiddles ----------------
__global__ void k_twiddle() {
    int k = blockIdx.x * 256 + threadIdx.x;
    double a = -2.0 * 3.14159265358979323846 * (double)k / (double)NFFT;
    g_tw[k] = make_float2((float)cos(a), (float)sin(a));
}

// ---------------- RoPE ----------------
__global__ void k_rope(const float* __restrict__ emb, const int* __restrict__ pos) {
    int idx = blockIdx.x * blockDim.x + threadIdx.x;
    if (idx >= Mr * 64) return;
    int j  = idx & 63;
    int bs = idx >> 6;
    float theta = powf(10000.0f, -(float)(2 * j) / 128.0f);
    float ang = (float)pos[bs] * theta;
    float sa, ca; sincosf(ang, &sa, &ca);
    float xe = emb[(size_t)bs * 128 + 2 * j];
    float xo = emb[(size_t)bs * 128 + 2 * j + 1];
    g_t[(size_t)bs * 128 + 2 * j]     = xe * ca - xo * sa;
    g_t[(size_t)bs * 128 + 2 * j + 1] = xe * sa + xo * ca;
}

// ---------------- depthwise conv K=3 along S ----------------
__global__ void k_conv(const float* __restrict__ w, const float* __restrict__ bias) {
    int idx = blockIdx.x * blockDim.x + threadIdx.x;
    if (idx >= Mr * GDc) return;
    int c  = idx % GDc;
    int bs = idx / GDc;
    int s  = bs & 8191;
    const float* xp = g_x + (size_t)bs * GDc + c;
    float acc = bias[c] + xp[0] * w[c * 3 + 1];
    if (s > 0)    acc += xp[-GDc] * w[c * 3 + 0];
    if (s < 8191) acc += xp[GDc]  * w[c * 3 + 2];
    g_zc[idx] = acc;
}

// ---------------- fused SGEMMs ----------------
// MODE 0: g_x = emb @ W_proj                       (NC=384)
// MODE 1: g_hmid = gelu(LN(g_t @ W1 + b1))         (NC=128)
// MODE 2: g_hT   = L1norm((g_hmid@W2+b2)*ffs), T   (NC=256)
// MODE 3: out    = v^T @ out_proj  (A k-major)     (NC=128)
template<int MODE>
__global__ __launch_bounds__(256)
void k_sgemm(const float* __restrict__ Aext, const float* __restrict__ W,
             const float* __restrict__ bias, const float* __restrict__ gain,
             const float* __restrict__ beta, float* __restrict__ Cext)
{
    constexpr int  NC   = (MODE == 0) ? 384 : (MODE == 2) ? 256 : 128;
    constexpr bool KMAJ = (MODE == 3);
    __shared__ float As[16 * 132];
    __shared__ float Bs[16 * 132];

    const int tid  = threadIdx.x;
    const int m0   = blockIdx.x * 128;
    const int n0   = blockIdx.y * 128;
    const int trow = tid >> 4;
    const int tcol = tid & 15;

    const float* A;
    float* C;
    if      (MODE == 0) { A = Aext;   C = g_x;    }
    else if (MODE == 1) { A = g_t;    C = g_hmid; }
    else if (MODE == 2) { A = g_hmid; C = nullptr;}
    else                { A = g_vT;   C = Cext;   }

    float acc[8][8];
#pragma unroll
    for (int i = 0; i < 8; i++)
#pragma unroll
        for (int j = 0; j < 8; j++) acc[i][j] = 0.f;

    const float* Ak = nullptr;
    if (KMAJ) Ak = A + (size_t)(m0 >> 13) * (128 * 8192) + (m0 & 8191);

    for (int kt = 0; kt < 128; kt += 16) {
        __syncthreads();
        if (KMAJ) {
            int kk = tid >> 5, c4 = tid & 31;
#pragma unroll
            for (int r2 = 0; r2 < 2; r2++) {
                int kr = kk + r2 * 8;
                float4 v = *(const float4*)(Ak + (size_t)(kt + kr) * 8192 + (c4 << 2));
                *(float4*)(As + kr * 132 + (c4 << 2)) = v;
            }
        } else {
            int rr = tid >> 2, c4 = tid & 3;
#pragma unroll
            for (int r2 = 0; r2 < 2; r2++) {
                int row = rr + (r2 << 6);
                float4 v = *(const float4*)(A + (size_t)(m0 + row) * 128 + kt + (c4 << 2));
                As[(c4 * 4 + 0) * 132 + row] = v.x;
                As[(c4 * 4 + 1) * 132 + row] = v.y;
                As[(c4 * 4 + 2) * 132 + row] = v.z;
                As[(c4 * 4 + 3) * 132 + row] = v.w;
            }
        }
        {
            int kk = tid >> 5, c4 = tid & 31;
#pragma unroll
            for (int r2 = 0; r2 < 2; r2++) {
                int kr = kk + r2 * 8;
                float4 v = *(const float4*)(W + (size_t)(kt + kr) * NC + n0 + (c4 << 2));
                *(float4*)(Bs + kr * 132 + (c4 << 2)) = v;
            }
        }
        __syncthreads();
#pragma unroll
        for (int kk = 0; kk < 16; kk++) {
            float4 a0 = *(const float4*)(As + kk * 132 + (trow << 2));
            float4 a1 = *(const float4*)(As + kk * 132 + (trow << 2) + 64);
            float4 b0 = *(const float4*)(Bs + kk * 132 + (tcol << 2));
            float4 b1 = *(const float4*)(Bs + kk * 132 + (tcol << 2) + 64);
            float av[8] = {a0.x, a0.y, a0.z, a0.w, a1.x, a1.y, a1.z, a1.w};
            float bv[8] = {b0.x, b0.y, b0.z, b0.w, b1.x, b1.y, b1.z, b1.w};
#pragma unroll
            for (int i = 0; i < 8; i++)
#pragma unroll
                for (int j = 0; j < 8; j++)
                    acc[i][j] = fmaf(av[i], bv[j], acc[i][j]);
        }
    }

    int colL[8];
#pragma unroll
    for (int j = 0; j < 8; j++) colL[j] = (tcol << 2) + (j < 4 ? j : 60 + j);

    if (MODE == 0 || MODE == 3) {
#pragma unroll
        for (int i = 0; i < 8; i++) {
            int row = (trow << 2) + (i < 4 ? i : 60 + i);
            float* cp = C + (size_t)(m0 + row) * NC + n0 + (tcol << 2);
            *(float4*)cp        = make_float4(acc[i][0], acc[i][1], acc[i][2], acc[i][3]);
            *(float4*)(cp + 64) = make_float4(acc[i][4], acc[i][5], acc[i][6], acc[i][7]);
        }
    } else if (MODE == 1) {
        float bj[8], gj[8], tj[8];
#pragma unroll
        for (int j = 0; j < 8; j++) { bj[j] = bias[colL[j]]; gj[j] = gain[colL[j]]; tj[j] = beta[colL[j]]; }
#pragma unroll
        for (int i = 0; i < 8; i++) {
            float s = 0.f, s2 = 0.f;
#pragma unroll
            for (int j = 0; j < 8; j++) {
                float x = acc[i][j] + bj[j];
                acc[i][j] = x; s += x; s2 += x * x;
            }
#pragma unroll
            for (int off = 1; off < 16; off <<= 1) {
                s  += __shfl_xor_sync(0xffffffffu, s,  off, 16);
                s2 += __shfl_xor_sync(0xffffffffu, s2, off, 16);
            }
            float mu  = s * (1.f / 128.f);
            float var = s2 * (1.f / 128.f) - mu * mu;
            float rs  = rsqrtf(var + 1e-5f);
            float o[8];
#pragma unroll
            for (int j = 0; j < 8; j++) {
                float xn = (acc[i][j] - mu) * rs * gj[j] + tj[j];
                o[j] = 0.5f * xn * (1.f + erff(xn * 0.70710678118654752f));
            }
            int row = (trow << 2) + (i < 4 ? i : 60 + i);
            float* cp = g_hmid + (size_t)(m0 + row) * 128 + (tcol << 2);
            *(float4*)cp        = make_float4(o[0], o[1], o[2], o[3]);
            *(float4*)(cp + 64) = make_float4(o[4], o[5], o[6], o[7]);
        }
    } else { // MODE 2
        float bj[8], gj[8];
#pragma unroll
        for (int j = 0; j < 8; j++) { bj[j] = bias[n0 + colL[j]]; gj[j] = gain[n0 + colL[j]]; }
        float rsc[8];
#pragma unroll
        for (int i = 0; i < 8; i++) {
            float s = 0.f;
#pragma unroll
            for (int j = 0; j < 8; j++) {
                float x = (acc[i][j] + bj[j]) * gj[j];
                acc[i][j] = x; s += fabsf(x);
            }
#pragma unroll
            for (int off = 1; off < 16; off <<= 1)
                s += __shfl_xor_sync(0xffffffffu, s, off, 16);
            rsc[i] = 1.f / (s + 1e-8f);
        }
        // transposed store to g_hT[b,n,d,s]; float4 along s
        float* dst = g_hT + (size_t)((m0 >> 13) * 2 + (n0 >> 7)) * 128 * 8192;
        int s0 = (m0 & 8191) + (trow << 2);
#pragma unroll
        for (int j = 0; j < 8; j++) {
            float* dp = dst + (size_t)colL[j] * 8192 + s0;
            *(float4*)dp = make_float4(acc[0][j] * rsc[0], acc[1][j] * rsc[1],
                                       acc[2][j] * rsc[2], acc[3][j] * rsc[3]);
            *(float4*)(dp + 64) = make_float4(acc[4][j] * rsc[4], acc[5][j] * rsc[5],
                                              acc[6][j] * rsc[6], acc[7][j] * rsc[7]);
        }
    }
}

// ---------------- FFT recurrence: 1 CTA per (b,d) ----------------
__global__ __launch_bounds__(1024)
void k_fftrec(const float* __restrict__ Bp) {
    extern __shared__ float2 sh[];
    int b = blockIdx.x >> 7, d = blockIdx.x & 127;
    int tid = threadIdx.x;
    const float* z = g_zc + (size_t)b * (8192 * 384) + (size_t)d * 24576;

    float v[8];
#pragma unroll
    for (int k = 0; k < 8; k++) v[k] = z[16384 + tid + k * 1024];

    for (int it = 0; it < 2; it++) {
        const float* h = g_hT + (size_t)((b * 2 + it) * 128 + d) * 8192;
        // pack p = v + i*h, zero-pad
#pragma unroll
        for (int k = 0; k < 8; k++) {
            int s = tid + k * 1024;
            sh[s]        = make_float2(v[k], h[s]);
            sh[s + 8192] = make_float2(0.f, 0.f);
        }
        __syncthreads();
        // forward DIF (natural in, bit-reversed out)
        for (int lg = 13; lg >= 0; lg--) {
            int len = 1 << lg;
#pragma unroll 1
            for (int jj = 0; jj < 8; jj++) {
                int j   = tid + jj * 1024;
                int off = j & (len - 1);
                int i   = ((j >> lg) << (lg + 1)) + off;
                float2 a  = sh[i], bb = sh[i + len];
                float2 t  = make_float2(a.x - bb.x, a.y - bb.y);
                float2 w  = g_tw[off << (13 - lg)];
                sh[i]       = make_float2(a.x + bb.x, a.y + bb.y);
                sh[i + len] = make_float2(t.x * w.x - t.y * w.y, t.x * w.y + t.y * w.x);
            }
            __syncthreads();
        }
        // spectral: U_k = V_k * H_k with Hermitian split, in bit-reversed layout
        float2 ur[16];
#pragma unroll
        for (int k = 0; k < 16; k++) {
            int p  = tid + k * 1024;
            int kk = __brev(p) >> 18;
            int k2 = (16384 - kk) & 16383;
            int p2 = __brev(k2) >> 18;
            float2 P = sh[p], Q = sh[p2];
            float vx = 0.5f * (P.x + Q.x), vy = 0.5f * (P.y - Q.y);
            float hx = 0.5f * (P.y + Q.y), hy = 0.5f * (Q.x - P.x);
            ur[k] = make_float2(vx * hx - vy * hy, vx * hy + vy * hx);
        }
        __syncthreads();
#pragma unroll
        for (int k = 0; k < 16; k++) sh[tid + k * 1024] = ur[k];
        __syncthreads();
        // inverse DIT (bit-reversed in, natural out), conj twiddles, unnormalized
        for (int lg = 0; lg <= 13; lg++) {
            int len = 1 << lg;
#pragma unroll 1
            for (int jj = 0; jj < 8; jj++) {
                int j   = tid + jj * 1024;
                int off = j & (len - 1);
                int i   = ((j >> lg) << (lg + 1)) + off;
                float2 a  = sh[i], bb = sh[i + len];
                float2 w  = g_tw[off << (13 - lg)];
                float2 t  = make_float2(bb.x * w.x + bb.y * w.y, bb.y * w.x - bb.x * w.y);
                sh[i]       = make_float2(a.x + t.x, a.y + t.y);
                sh[i + len] = make_float2(a.x - t.x, a.y - t.y);
            }
            __syncthreads();
        }
        // v = z_it * (u + B_it * v)
        const float* zn = z + it * 8192;
        float Bn = Bp[it * 128 + d];
#pragma unroll
        for (int k = 0; k < 8; k++) {
            int s = tid + k * 1024;
            float u = sh[s].x * SCALE_U;
            v[k] = zn[s] * (u + Bn * v[k]);
        }
        __syncthreads();
    }
    float* vo = g_vT + (size_t)(b * 128 + d) * 8192;
#pragma unroll
    for (int k = 0; k < 8; k++) vo[tid + k * 1024] = v[k];
}

extern "C" void kernel_launch(void* const* d_in, const int* in_sizes, int n_in,
                              void* d_out, int out_size) {
    const float* emb = (const float*)d_in[0];
    const float* Wp  = (const float*)d_in[1];
    const float* cw  = (const float*)d_in[2];
    const float* cb  = (const float*)d_in[3];
    const float* W1  = (const float*)d_in[4];
    const float* b1  = (const float*)d_in[5];
    const float* lng = (const float*)d_in[6];
    const float* lnb = (const float*)d_in[7];
    const float* W2  = (const float*)d_in[8];
    const float* b2  = (const float*)d_in[9];
    const float* ffs = (const float*)d_in[10];
    const float* op  = (const float*)d_in[11];
    const float* Bp  = (const float*)d_in[12];
    const int*   pos = (const int*)d_in[13];
    float* out = (float*)d_out;

    cudaFuncSetAttribute(k_fftrec, cudaFuncAttributeMaxDynamicSharedMemorySize, 131072);

    k_twiddle<<<32, 256>>>();
    k_sgemm<0><<<dim3(256, 3), 256>>>(emb, Wp, nullptr, nullptr, nullptr, nullptr);
    k_conv<<<49152, 256>>>(cw, cb);
    k_rope<<<8192, 256>>>(emb, pos);
    k_sgemm<1><<<dim3(256, 1), 256>>>(nullptr, W1, b1, lng, lnb, nullptr);
    k_sgemm<2><<<dim3(256, 2), 256>>>(nullptr, W2, b2, ffs, nullptr, nullptr);
    k_fftrec<<<512, 1024, 131072>>>(Bp);
    k_sgemm<3><<<dim3(256, 1), 256>>>(nullptr, op, nullptr, nullptr, nullptr, out);
}

// round 3
// speedup vs baseline: 2.3467x; 2.3467x over previous
#include <cuda_runtime.h>
#include <math.h>

#define Mr 32768
#define GDc 384
#define NFFT 16384
#define HALFN 8192
#define SCALE_U (1.0f / (16384.0f * 16384.0f))

// smem physical index swizzle: inject bits [4:5] into [0:1] and [2:3]
__device__ __forceinline__ int PH(int e) {
    int m = (e >> 4) & 3;
    return e ^ (m | (m << 2));
}
__device__ __forceinline__ float2 cmul(float2 a, float2 b) {
    return make_float2(a.x * b.x - a.y * b.y, a.x * b.y + a.y * b.x);
}
__device__ __forceinline__ float2 cadd(float2 a, float2 b) { return make_float2(a.x + b.x, a.y + b.y); }
__device__ __forceinline__ float2 csub(float2 a, float2 b) { return make_float2(a.x - b.x, a.y - b.y); }

// ---------------- scratch (device globals) ----------------
__device__ float  g_x   [(long long)Mr * GDc];          // emb @ W_proj [B,S,384]
__device__ float  g_zc  [(long long)Mr * GDc];          // conv out     [B,S,384]
__device__ float  g_t   [(long long)Mr * 128];          // rope(emb)
__device__ float  g_hmid[(long long)Mr * 128];          // gelu(LN(...))
__device__ float  g_hT  [(long long)4 * 2 * 128 * 8192];// h normalized [B,N,D,S]
__device__ float  g_vT  [(long long)4 * 128 * 8192];    // recurrence   [B,D,S]
__device__ float2 g_tw  [HALFN];                        // W_N^k

// ---------------- twiddles ----------------
__global__ void k_twiddle() {
    int k = blockIdx.x * 256 + threadIdx.x;
    double a = -2.0 * 3.14159265358979323846 * (double)k / (double)NFFT;
    g_tw[k] = make_float2((float)cos(a), (float)sin(a));
}

// ---------------- RoPE ----------------
__global__ void k_rope(const float* __restrict__ emb, const int* __restrict__ pos) {
    int idx = blockIdx.x * blockDim.x + threadIdx.x;
    if (idx >= Mr * 64) return;
    int j  = idx & 63;
    int bs = idx >> 6;
    // theta = 10000^(-2j/128) = 2^(-j * log2(10000)/64)
    float theta = exp2f(-(float)j * 0.20762050593046015f);
    float ang = (float)pos[bs] * theta;
    float sa, ca; sincosf(ang, &sa, &ca);
    float2 xv = *(const float2*)(emb + (size_t)bs * 128 + 2 * j);
    float2 o;
    o.x = xv.x * ca - xv.y * sa;
    o.y = xv.x * sa + xv.y * ca;
    *(float2*)(g_t + (size_t)bs * 128 + 2 * j) = o;
}

// ---------------- depthwise conv K=3 along S ----------------
__global__ void k_conv(const float* __restrict__ w, const float* __restrict__ bias) {
    int idx = blockIdx.x * blockDim.x + threadIdx.x;
    if (idx >= Mr * GDc) return;
    int c  = idx % GDc;
    int bs = idx / GDc;
    int s  = bs & 8191;
    const float* xp = g_x + (size_t)bs * GDc + c;
    float acc = bias[c] + xp[0] * w[c * 3 + 1];
    if (s > 0)    acc += xp[-GDc] * w[c * 3 + 0];
    if (s < 8191) acc += xp[GDc]  * w[c * 3 + 2];
    g_zc[idx] = acc;
}

// ---------------- fused SGEMMs ----------------
// MODE 0: g_x = emb @ W_proj                       (NC=384)
// MODE 1: g_hmid = gelu(LN(g_t @ W1 + b1))         (NC=128)
// MODE 2: g_hT   = L1norm((g_hmid@W2+b2)*ffs), T   (NC=256)
// MODE 3: out    = v^T @ out_proj  (A k-major)     (NC=128)
template<int MODE>
__global__ __launch_bounds__(256)
void k_sgemm(const float* __restrict__ Aext, const float* __restrict__ W,
             const float* __restrict__ bias, const float* __restrict__ gain,
             const float* __restrict__ beta, float* __restrict__ Cext)
{
    constexpr int  NC   = (MODE == 0) ? 384 : (MODE == 2) ? 256 : 128;
    constexpr bool KMAJ = (MODE == 3);
    __shared__ float As[16 * 132];
    __shared__ float Bs[16 * 132];

    const int tid  = threadIdx.x;
    const int m0   = blockIdx.x * 128;
    const int n0   = blockIdx.y * 128;
    const int trow = tid >> 4;
    const int tcol = tid & 15;

    const float* A;
    float* C;
    if      (MODE == 0) { A = Aext;   C = g_x;    }
    else if (MODE == 1) { A = g_t;    C = g_hmid; }
    else if (MODE == 2) { A = g_hmid; C = nullptr;}
    else                { A = g_vT;   C = Cext;   }

    float acc[8][8];
#pragma unroll
    for (int i = 0; i < 8; i++)
#pragma unroll
        for (int j = 0; j < 8; j++) acc[i][j] = 0.f;

    const float* Ak = nullptr;
    if (KMAJ) Ak = A + (size_t)(m0 >> 13) * (128 * 8192) + (m0 & 8191);

    for (int kt = 0; kt < 128; kt += 16) {
        __syncthreads();
        if (KMAJ) {
            int kk = tid >> 5, c4 = tid & 31;
#pragma unroll
            for (int r2 = 0; r2 < 2; r2++) {
                int kr = kk + r2 * 8;
                float4 v = *(const float4*)(Ak + (size_t)(kt + kr) * 8192 + (c4 << 2));
                *(float4*)(As + kr * 132 + (c4 << 2)) = v;
            }
        } else {
            int rr = tid >> 2, c4 = tid & 3;
#pragma unroll
            for (int r2 = 0; r2 < 2; r2++) {
                int row = rr + (r2 << 6);
                float4 v = *(const float4*)(A + (size_t)(m0 + row) * 128 + kt + (c4 << 2));
                As[(c4 * 4 + 0) * 132 + row] = v.x;
                As[(c4 * 4 + 1) * 132 + row] = v.y;
                As[(c4 * 4 + 2) * 132 + row] = v.z;
                As[(c4 * 4 + 3) * 132 + row] = v.w;
            }
        }
        {
            int kk = tid >> 5, c4 = tid & 31;
#pragma unroll
            for (int r2 = 0; r2 < 2; r2++) {
                int kr = kk + r2 * 8;
                float4 v = *(const float4*)(W + (size_t)(kt + kr) * NC + n0 + (c4 << 2));
                *(float4*)(Bs + kr * 132 + (c4 << 2)) = v;
            }
        }
        __syncthreads();
#pragma unroll
        for (int kk = 0; kk < 16; kk++) {
            float4 a0 = *(const float4*)(As + kk * 132 + (trow << 2));
            float4 a1 = *(const float4*)(As + kk * 132 + (trow << 2) + 64);
            float4 b0 = *(const float4*)(Bs + kk * 132 + (tcol << 2));
            float4 b1 = *(const float4*)(Bs + kk * 132 + (tcol << 2) + 64);
            float av[8] = {a0.x, a0.y, a0.z, a0.w, a1.x, a1.y, a1.z, a1.w};
            float bv[8] = {b0.x, b0.y, b0.z, b0.w, b1.x, b1.y, b1.z, b1.w};
#pragma unroll
            for (int i = 0; i < 8; i++)
#pragma unroll
                for (int j = 0; j < 8; j++)
                    acc[i][j] = fmaf(av[i], bv[j], acc[i][j]);
        }
    }

    int colL[8];
#pragma unroll
    for (int j = 0; j < 8; j++) colL[j] = (tcol << 2) + (j < 4 ? j : 60 + j);

    if (MODE == 0 || MODE == 3) {
#pragma unroll
        for (int i = 0; i < 8; i++) {
            int row = (trow << 2) + (i < 4 ? i : 60 + i);
            float* cp = C + (size_t)(m0 + row) * NC + n0 + (tcol << 2);
            *(float4*)cp        = make_float4(acc[i][0], acc[i][1], acc[i][2], acc[i][3]);
            *(float4*)(cp + 64) = make_float4(acc[i][4], acc[i][5], acc[i][6], acc[i][7]);
        }
    } else if (MODE == 1) {
        float bj[8], gj[8], tj[8];
#pragma unroll
        for (int j = 0; j < 8; j++) { bj[j] = bias[colL[j]]; gj[j] = gain[colL[j]]; tj[j] = beta[colL[j]]; }
#pragma unroll
        for (int i = 0; i < 8; i++) {
            float s = 0.f, s2 = 0.f;
#pragma unroll
            for (int j = 0; j < 8; j++) {
                float x = acc[i][j] + bj[j];
                acc[i][j] = x; s += x; s2 += x * x;
            }
#pragma unroll
            for (int off = 1; off < 16; off <<= 1) {
                s  += __shfl_xor_sync(0xffffffffu, s,  off, 16);
                s2 += __shfl_xor_sync(0xffffffffu, s2, off, 16);
            }
            float mu  = s * (1.f / 128.f);
            float var = s2 * (1.f / 128.f) - mu * mu;
            float rs  = rsqrtf(var + 1e-5f);
            float o[8];
#pragma unroll
            for (int j = 0; j < 8; j++) {
                float xn = (acc[i][j] - mu) * rs * gj[j] + tj[j];
                o[j] = 0.5f * xn * (1.f + erff(xn * 0.70710678118654752f));
            }
            int row = (trow << 2) + (i < 4 ? i : 60 + i);
            float* cp = g_hmid + (size_t)(m0 + row) * 128 + (tcol << 2);
            *(float4*)cp        = make_float4(o[0], o[1], o[2], o[3]);
            *(float4*)(cp + 64) = make_float4(o[4], o[5], o[6], o[7]);
        }
    } else { // MODE 2
        float bj[8], gj[8];
#pragma unroll
        for (int j = 0; j < 8; j++) { bj[j] = bias[n0 + colL[j]]; gj[j] = gain[n0 + colL[j]]; }
        float rsc[8];
#pragma unroll
        for (int i = 0; i < 8; i++) {
            float s = 0.f;
#pragma unroll
            for (int j = 0; j < 8; j++) {
                float x = (acc[i][j] + bj[j]) * gj[j];
                acc[i][j] = x; s += fabsf(x);
            }
#pragma unroll
            for (int off = 1; off < 16; off <<= 1)
                s += __shfl_xor_sync(0xffffffffu, s, off, 16);
            rsc[i] = 1.f / (s + 1e-8f);
        }
        float* dst = g_hT + (size_t)((m0 >> 13) * 2 + (n0 >> 7)) * 128 * 8192;
        int s0 = (m0 & 8191) + (trow << 2);
#pragma unroll
        for (int j = 0; j < 8; j++) {
            float* dp = dst + (size_t)colL[j] * 8192 + s0;
            *(float4*)dp = make_float4(acc[0][j] * rsc[0], acc[1][j] * rsc[1],
                                       acc[2][j] * rsc[2], acc[3][j] * rsc[3]);
            *(float4*)(dp + 64) = make_float4(acc[4][j] * rsc[4], acc[5][j] * rsc[5],
                                              acc[6][j] * rsc[6], acc[7][j] * rsc[7]);
        }
    }
}

// ---------------- FFT recurrence: 1 CTA per (b,d), radix-4 passes ----------------
__global__ __launch_bounds__(1024)
void k_fftrec(const float* __restrict__ Bp) {
    extern __shared__ float2 sh[];
    int b = blockIdx.x >> 7, d = blockIdx.x & 127;
    int tid = threadIdx.x;
    const float* z = g_zc + (size_t)b * (8192 * 384) + (size_t)d * 24576;

    float v[8];
#pragma unroll
    for (int k = 0; k < 8; k++) v[k] = z[16384 + tid + k * 1024];

    for (int it = 0; it < 2; it++) {
        const float* h = g_hT + (size_t)((b * 2 + it) * 128 + d) * 8192;

        // ---- forward pass 1 (lg=13) fused with packing; upper half is zero ----
#pragma unroll
        for (int jj = 0; jj < 4; jj++) {
            int j = tid + jj * 1024;
            float2 x0 = make_float2(v[jj],     h[j]);
            float2 x1 = make_float2(v[jj + 4], h[j + 4096]);
            float2 W1 = g_tw[j];
            float2 W2 = make_float2(W1.y, -W1.x);      // -i*W1
            float2 W3 = cmul(W1, W1);
            float2 t02m = cmul(x0, W1);
            float2 t13m = cmul(x1, W2);
            sh[PH(j)]         = cadd(x0, x1);
            sh[PH(j + 4096)]  = cmul(csub(x0, x1), W3);
            sh[PH(j + 8192)]  = cadd(t02m, t13m);
            sh[PH(j + 12288)] = cmul(csub(t02m, t13m), W3);
        }
        __syncthreads();

        // ---- forward radix-4 passes: lg = 11,9,7,5,3,1 ----
#pragma unroll
        for (int lg = 11; lg >= 1; lg -= 2) {
            int half = 1 << (lg - 1);
#pragma unroll
            for (int jj = 0; jj < 4; jj++) {
                int j   = tid + jj * 1024;
                int off = j & (half - 1);
                int i   = ((j >> (lg - 1)) << (lg + 1)) + off;
                float2 x0 = sh[PH(i)];
                float2 x1 = sh[PH(i + half)];
                float2 x2 = sh[PH(i + 2 * half)];
                float2 x3 = sh[PH(i + 3 * half)];
                float2 W1 = g_tw[off << (13 - lg)];
                float2 W2 = make_float2(W1.y, -W1.x);
                float2 W3 = cmul(W1, W1);
                float2 t02p = cadd(x0, x2);
                float2 t02m = cmul(csub(x0, x2), W1);
                float2 t13p = cadd(x1, x3);
                float2 t13m = cmul(csub(x1, x3), W2);
                sh[PH(i)]            = cadd(t02p, t13p);
                sh[PH(i + half)]     = cmul(csub(t02p, t13p), W3);
                sh[PH(i + 2 * half)] = cadd(t02m, t13m);
                sh[PH(i + 3 * half)] = cmul(csub(t02m, t13m), W3);
            }
            __syncthreads();
        }

        // ---- spectral multiply (bit-reversed layout, Hermitian split) ----
        float2 ur[16];
#pragma unroll
        for (int k = 0; k < 16; k++) {
            int p  = tid + k * 1024;
            int kk = __brev(p) >> 18;
            int k2 = (16384 - kk) & 16383;
            int p2 = __brev(k2) >> 18;
            float2 P = sh[PH(p)], Q = sh[PH(p2)];
            float vx = 0.5f * (P.x + Q.x), vy = 0.5f * (P.y - Q.y);
            float hx = 0.5f * (P.y + Q.y), hy = 0.5f * (Q.x - P.x);
            ur[k] = make_float2(vx * hx - vy * hy, vx * hy + vy * hx);
        }
        __syncthreads();
#pragma unroll
        for (int k = 0; k < 16; k++) sh[PH(tid + k * 1024)] = ur[k];
        __syncthreads();

        // ---- inverse radix-4 passes: lg = 0,2,4,6,8,10 ----
#pragma unroll
        for (int lg = 0; lg <= 10; lg += 2) {
            int len = 1 << lg;
#pragma unroll
            for (int jj = 0; jj < 4; jj++) {
                int j   = tid + jj * 1024;
                int off = j & (len - 1);
                int i   = ((j >> lg) << (lg + 2)) + off;
                float2 x0 = sh[PH(i)];
                float2 x1 = sh[PH(i + len)];
                float2 x2 = sh[PH(i + 2 * len)];
                float2 x3 = sh[PH(i + 3 * len)];
                float2 w   = g_tw[off << (12 - lg)];
                float2 cw2 = make_float2(w.x, -w.y);
                float2 cw1 = cmul(cw2, cw2);
                float2 cw3 = make_float2(-cw2.y, cw2.x); // i*cw2
                float2 b1 = cmul(x1, cw1);
                float2 b3 = cmul(x3, cw1);
                float2 u0 = cadd(x0, b1), u1 = csub(x0, b1);
                float2 u2 = cadd(x2, b3), u3 = csub(x2, b3);
                float2 c2 = cmul(u2, cw2);
                float2 c3 = cmul(u3, cw3);
                sh[PH(i)]           = cadd(u0, c2);
                sh[PH(i + 2 * len)] = csub(u0, c2);
                sh[PH(i + len)]     = cadd(u1, c3);
                sh[PH(i + 3 * len)] = csub(u1, c3);
            }
            __syncthreads();
        }

        // ---- final inverse pass (lg=12) fused with v-update; only real parts of s<8192 ----
        const float* zn = z + it * 8192;
        float Bn = Bp[it * 128 + d];
#pragma unroll
        for (int jj = 0; jj < 4; jj++) {
            int j = tid + jj * 1024;   // off = j, i = j
            float2 x0 = sh[PH(j)];
            float2 x1 = sh[PH(j + 4096)];
            float2 x2 = sh[PH(j + 8192)];
            float2 x3 = sh[PH(j + 12288)];
            float2 w   = g_tw[j];
            float2 cw2 = make_float2(w.x, -w.y);
            float2 cw1 = cmul(cw2, cw2);
            float2 cw3 = make_float2(-cw2.y, cw2.x);
            float2 b1 = cmul(x1, cw1);
            float2 b3 = cmul(x3, cw1);
            float2 u0 = cadd(x0, b1), u1 = csub(x0, b1);
            float2 u2 = cadd(x2, b3), u3 = csub(x2, b3);
            float y0x = u0.x + (u2.x * cw2.x - u2.y * cw2.y);
            float y1x = u1.x + (u3.x * cw3.x - u3.y * cw3.y);
            v[jj]     = zn[j]        * (y0x * SCALE_U + Bn * v[jj]);
            v[jj + 4] = zn[j + 4096] * (y1x * SCALE_U + Bn * v[jj + 4]);
        }
        __syncthreads();
    }
    float* vo = g_vT + (size_t)(b * 128 + d) * 8192;
#pragma unroll
    for (int k = 0; k < 8; k++) vo[tid + k * 1024] = v[k];
}

extern "C" void kernel_launch(void* const* d_in, const int* in_sizes, int n_in,
                              void* d_out, int out_size) {
    const float* emb = (const float*)d_in[0];
    const float* Wp  = (const float*)d_in[1];
    const float* cw  = (const float*)d_in[2];
    const float* cb  = (const float*)d_in[3];
    const float* W1  = (const float*)d_in[4];
    const float* b1  = (const float*)d_in[5];
    const float* lng = (const float*)d_in[6];
    const float* lnb = (const float*)d_in[7];
    const float* W2  = (const float*)d_in[8];
    const float* b2  = (const float*)d_in[9];
    const float* ffs = (const float*)d_in[10];
    const float* op  = (const float*)d_in[11];
    const float* Bp  = (const float*)d_in[12];
    const int*   pos = (const int*)d_in[13];
    float* out = (float*)d_out;

    cudaFuncSetAttribute(k_fftrec, cudaFuncAttributeMaxDynamicSharedMemorySize, 131072);

    k_twiddle<<<32, 256>>>();
    k_sgemm<0><<<dim3(256, 3), 256>>>(emb, Wp, nullptr, nullptr, nullptr, nullptr);
    k_conv<<<49152, 256>>>(cw, cb);
    k_rope<<<8192, 256>>>(emb, pos);
    k_sgemm<1><<<dim3(256, 1), 256>>>(nullptr, W1, b1, lng, lnb, nullptr);
    k_sgemm<2><<<dim3(256, 2), 256>>>(nullptr, W2, b2, ffs, nullptr, nullptr);
    k_fftrec<<<512, 1024, 131072>>>(Bp);
    k_sgemm<3><<<dim3(256, 1), 256>>>(nullptr, op, nullptr, nullptr, nullptr, out);
}

// round 5
// speedup vs baseline: 2.5280x; 1.0772x over previous
#include <cuda_runtime.h>
#include <math.h>

#define Mr 32768
#define GDc 384
#define NFFT 16384
#define HALFN 8192
#define SCALE_U (1.0f / (16384.0f * 16384.0f))

// smem physical index swizzle: inject bits [4:5] into [0:1] and [2:3]
__device__ __forceinline__ int PH(int e) {
    int m = (e >> 4) & 3;
    return e ^ (m | (m << 2));
}
__device__ __forceinline__ float2 cmul(float2 a, float2 b) {
    return make_float2(a.x * b.x - a.y * b.y, a.x * b.y + a.y * b.x);
}
__device__ __forceinline__ float2 cadd(float2 a, float2 b) { return make_float2(a.x + b.x, a.y + b.y); }
__device__ __forceinline__ float2 csub(float2 a, float2 b) { return make_float2(a.x - b.x, a.y - b.y); }

// ---- packed f32x2 helpers (Blackwell FFMA2) ----
__device__ __forceinline__ unsigned long long pk2(float lo, float hi) {
    unsigned long long r;
    asm("mov.b64 %0, {%1, %2};" : "=l"(r) : "f"(lo), "f"(hi));
    return r;
}
__device__ __forceinline__ void upk2(float& lo, float& hi, unsigned long long v) {
    asm("mov.b64 {%0, %1}, %2;" : "=f"(lo), "=f"(hi) : "l"(v));
}
__device__ __forceinline__ void fma2(unsigned long long& d, unsigned long long a, unsigned long long b) {
    asm("fma.rn.f32x2 %0, %1, %2, %0;" : "+l"(d) : "l"(a), "l"(b));
}

// ---------------- scratch (device globals) ----------------
__device__ float  g_x   [(long long)Mr * GDc];          // emb @ W_proj [B,S,384]
__device__ float  g_zc  [(long long)Mr * GDc];          // conv out     [B,S,384]
__device__ float  g_t   [(long long)Mr * 128];          // rope(emb)
__device__ float  g_hmid[(long long)Mr * 128];          // gelu(LN(...))
__device__ float  g_hT  [(long long)4 * 2 * 128 * 8192];// h normalized [B,N,D,S]
__device__ float  g_vT  [(long long)4 * 128 * 8192];    // recurrence   [B,D,S]
__device__ float2 g_tw  [HALFN];                        // W_N^k

// ---------------- twiddles ----------------
__global__ void k_twiddle() {
    int k = blockIdx.x * 256 + threadIdx.x;
    double a = -2.0 * 3.14159265358979323846 * (double)k / (double)NFFT;
    g_tw[k] = make_float2((float)cos(a), (float)sin(a));
}

// ---------------- RoPE ----------------
__global__ void k_rope(const float* __restrict__ emb, const int* __restrict__ pos) {
    int idx = blockIdx.x * blockDim.x + threadIdx.x;
    if (idx >= Mr * 64) return;
    int j  = idx & 63;
    int bs = idx >> 6;
    float theta = exp2f(-(float)j * 0.20762050593046015f);
    float ang = (float)pos[bs] * theta;
    float sa, ca; sincosf(ang, &sa, &ca);
    float2 xv = *(const float2*)(emb + (size_t)bs * 128 + 2 * j);
    float2 o;
    o.x = xv.x * ca - xv.y * sa;
    o.y = xv.x * sa + xv.y * ca;
    *(float2*)(g_t + (size_t)bs * 128 + 2 * j) = o;
}

// ---------------- depthwise conv K=3 along S (float4 over channels) ----------------
__global__ __launch_bounds__(256)
void k_conv(const float* __restrict__ w, const float* __restrict__ bias) {
    __shared__ float ws[3 * 384];
    __shared__ float bs_[384];
    int t = threadIdx.x;
    for (int i = t; i < 384; i += 256) bs_[i] = bias[i];
    for (int i = t; i < 1152; i += 256) ws[i] = w[i];
    __syncthreads();

    int idx = blockIdx.x * 256 + t;
    if (idx >= Mr * 96) return;
    int cg = idx % 96;
    int bs = idx / 96;
    int s  = bs & 8191;
    int c  = cg * 4;
    const float* xp = g_x + (size_t)bs * GDc + c;
    float4 x1 = *(const float4*)xp;
    float4 acc;
    acc.x = bs_[c + 0] + x1.x * ws[(c + 0) * 3 + 1];
    acc.y = bs_[c + 1] + x1.y * ws[(c + 1) * 3 + 1];
    acc.z = bs_[c + 2] + x1.z * ws[(c + 2) * 3 + 1];
    acc.w = bs_[c + 3] + x1.w * ws[(c + 3) * 3 + 1];
    if (s > 0) {
        float4 x0 = *(const float4*)(xp - GDc);
        acc.x += x0.x * ws[(c + 0) * 3];
        acc.y += x0.y * ws[(c + 1) * 3];
        acc.z += x0.z * ws[(c + 2) * 3];
        acc.w += x0.w * ws[(c + 3) * 3];
    }
    if (s < 8191) {
        float4 x2 = *(const float4*)(xp + GDc);
        acc.x += x2.x * ws[(c + 0) * 3 + 2];
        acc.y += x2.y * ws[(c + 1) * 3 + 2];
        acc.z += x2.z * ws[(c + 2) * 3 + 2];
        acc.w += x2.w * ws[(c + 3) * 3 + 2];
    }
    *(float4*)(g_zc + (size_t)bs * GDc + c) = acc;
}

// ---------------- fused SGEMMs (packed f32x2 FMA + gmem prefetch) ----------------
// MODE 0: g_x = emb @ W_proj                       (NC=384)
// MODE 1: g_hmid = gelu(LN(g_t @ W1 + b1))         (NC=128)
// MODE 2: g_hT   = L1norm((g_hmid@W2+b2)*ffs), T   (NC=256)
// MODE 3: out    = v^T @ out_proj  (A k-major)     (NC=128)
template<int MODE>
__global__ __launch_bounds__(256)
void k_sgemm(const float* __restrict__ Aext, const float* __restrict__ W,
             const float* __restrict__ bias, const float* __restrict__ gain,
             const float* __restrict__ beta, float* __restrict__ Cext)
{
    constexpr int  NC   = (MODE == 0) ? 384 : (MODE == 2) ? 256 : 128;
    constexpr bool KMAJ = (MODE == 3);
    __shared__ float As[16 * 132];
    __shared__ float Bs[16 * 132];

    const int tid  = threadIdx.x;
    const int m0   = blockIdx.x * 128;
    const int n0   = blockIdx.y * 128;
    const int trow = tid >> 4;
    const int tcol = tid & 15;

    const float* A;
    if      (MODE == 0) A = Aext;
    else if (MODE == 1) A = g_t;
    else if (MODE == 2) A = g_hmid;
    else                A = g_vT;

    const float* Ak = nullptr;
    if (KMAJ) Ak = A + (size_t)(m0 >> 13) * (128 * 8192) + (m0 & 8191);

    float4 aR[2], bR[2];
    const int arr = tid >> 2, ac4 = tid & 3;
    const int kk8 = tid >> 5, c32 = tid & 31;

    auto fetch = [&](int kt) {
        if (KMAJ) {
#pragma unroll
            for (int r2 = 0; r2 < 2; r2++)
                aR[r2] = *(const float4*)(Ak + (size_t)(kt + kk8 + r2 * 8) * 8192 + (c32 << 2));
        } else {
#pragma unroll
            for (int r2 = 0; r2 < 2; r2++)
                aR[r2] = *(const float4*)(A + (size_t)(m0 + arr + (r2 << 6)) * 128 + kt + (ac4 << 2));
        }
#pragma unroll
        for (int r2 = 0; r2 < 2; r2++)
            bR[r2] = *(const float4*)(W + (size_t)(kt + kk8 + r2 * 8) * NC + n0 + (c32 << 2));
    };
    auto stage = [&]() {
        if (KMAJ) {
#pragma unroll
            for (int r2 = 0; r2 < 2; r2++)
                *(float4*)(As + (kk8 + r2 * 8) * 132 + (c32 << 2)) = aR[r2];
        } else {
#pragma unroll
            for (int r2 = 0; r2 < 2; r2++) {
                int row = arr + (r2 << 6);
                As[(ac4 * 4 + 0) * 132 + row] = aR[r2].x;
                As[(ac4 * 4 + 1) * 132 + row] = aR[r2].y;
                As[(ac4 * 4 + 2) * 132 + row] = aR[r2].z;
                As[(ac4 * 4 + 3) * 132 + row] = aR[r2].w;
            }
        }
#pragma unroll
        for (int r2 = 0; r2 < 2; r2++)
            *(float4*)(Bs + (kk8 + r2 * 8) * 132 + (c32 << 2)) = bR[r2];
    };

    unsigned long long acc2[8][4];
#pragma unroll
    for (int i = 0; i < 8; i++)
#pragma unroll
        for (int j = 0; j < 4; j++) acc2[i][j] = 0ull;

    fetch(0);
#pragma unroll 1
    for (int t8 = 0; t8 < 8; t8++) {
        stage();
        __syncthreads();
        if (t8 < 7) fetch((t8 + 1) * 16);
#pragma unroll
        for (int kk = 0; kk < 16; kk++) {
            float4 a0 = *(const float4*)(As + kk * 132 + (trow << 2));
            float4 a1 = *(const float4*)(As + kk * 132 + (trow << 2) + 64);
            float4 b0 = *(const float4*)(Bs + kk * 132 + (tcol << 2));
            float4 b1 = *(const float4*)(Bs + kk * 132 + (tcol << 2) + 64);
            unsigned long long bp[4] = { pk2(b0.x, b0.y), pk2(b0.z, b0.w),
                                         pk2(b1.x, b1.y), pk2(b1.z, b1.w) };
            float av[8] = {a0.x, a0.y, a0.z, a0.w, a1.x, a1.y, a1.z, a1.w};
#pragma unroll
            for (int i = 0; i < 8; i++) {
                unsigned long long ap = pk2(av[i], av[i]);
#pragma unroll
                for (int j = 0; j < 4; j++) fma2(acc2[i][j], ap, bp[j]);
            }
        }
        __syncthreads();
    }

    float acc[8][8];
#pragma unroll
    for (int i = 0; i < 8; i++)
#pragma unroll
        for (int j = 0; j < 4; j++) upk2(acc[i][2 * j], acc[i][2 * j + 1], acc2[i][j]);

    int colL[8];
#pragma unroll
    for (int j = 0; j < 8; j++) colL[j] = (tcol << 2) + (j < 4 ? j : 60 + j);

    if (MODE == 0 || MODE == 3) {
        float* C = (MODE == 0) ? g_x : Cext;
#pragma unroll
        for (int i = 0; i < 8; i++) {
            int row = (trow << 2) + (i < 4 ? i : 60 + i);
            float* cp = C + (size_t)(m0 + row) * NC + n0 + (tcol << 2);
            *(float4*)cp        = make_float4(acc[i][0], acc[i][1], acc[i][2], acc[i][3]);
            *(float4*)(cp + 64) = make_float4(acc[i][4], acc[i][5], acc[i][6], acc[i][7]);
        }
    } else if (MODE == 1) {
        float bj[8], gj[8], tj[8];
#pragma unroll
        for (int j = 0; j < 8; j++) { bj[j] = bias[colL[j]]; gj[j] = gain[colL[j]]; tj[j] = beta[colL[j]]; }
#pragma unroll
        for (int i = 0; i < 8; i++) {
            float s = 0.f, s2 = 0.f;
#pragma unroll
            for (int j = 0; j < 8; j++) {
                float x = acc[i][j] + bj[j];
                acc[i][j] = x; s += x; s2 += x * x;
            }
#pragma unroll
            for (int off = 1; off < 16; off <<= 1) {
                s  += __shfl_xor_sync(0xffffffffu, s,  off, 16);
                s2 += __shfl_xor_sync(0xffffffffu, s2, off, 16);
            }
            float mu  = s * (1.f / 128.f);
            float var = s2 * (1.f / 128.f) - mu * mu;
            float rs  = rsqrtf(var + 1e-5f);
            float o[8];
#pragma unroll
            for (int j = 0; j < 8; j++) {
                float xn = (acc[i][j] - mu) * rs * gj[j] + tj[j];
                o[j] = 0.5f * xn * (1.f + erff(xn * 0.70710678118654752f));
            }
            int row = (trow << 2) + (i < 4 ? i : 60 + i);
            float* cp = g_hmid + (size_t)(m0 + row) * 128 + (tcol << 2);
            *(float4*)cp        = make_float4(o[0], o[1], o[2], o[3]);
            *(float4*)(cp + 64) = make_float4(o[4], o[5], o[6], o[7]);
        }
    } else { // MODE 2
        float bj[8], gj[8];
#pragma unroll
        for (int j = 0; j < 8; j++) { bj[j] = bias[n0 + colL[j]]; gj[j] = gain[n0 + colL[j]]; }
        float rsc[8];
#pragma unroll
        for (int i = 0; i < 8; i++) {
            float s = 0.f;
#pragma unroll
            for (int j = 0; j < 8; j++) {
                float x = (acc[i][j] + bj[j]) * gj[j];
                acc[i][j] = x; s += fabsf(x);
            }
#pragma unroll
            for (int off = 1; off < 16; off <<= 1)
                s += __shfl_xor_sync(0xffffffffu, s, off, 16);
            rsc[i] = 1.f / (s + 1e-8f);
        }
        float* dst = g_hT + (size_t)((m0 >> 13) * 2 + (n0 >> 7)) * 128 * 8192;
        int s0 = (m0 & 8191) + (trow << 2);
#pragma unroll
        for (int j = 0; j < 8; j++) {
            float* dp = dst + (size_t)colL[j] * 8192 + s0;
            *(float4*)dp = make_float4(acc[0][j] * rsc[0], acc[1][j] * rsc[1],
                                       acc[2][j] * rsc[2], acc[3][j] * rsc[3]);
            *(float4*)(dp + 64) = make_float4(acc[4][j] * rsc[4], acc[5][j] * rsc[5],
                                              acc[6][j] * rsc[6], acc[7][j] * rsc[7]);
        }
    }
}

// ---------------- FFT recurrence: 1 CTA per (b,d), radix-4 passes ----------------
__global__ __launch_bounds__(1024)
void k_fftrec(const float* __restrict__ Bp) {
    extern __shared__ float2 sh[];
    int b = blockIdx.x >> 7, d = blockIdx.x & 127;
    int tid = threadIdx.x;
    const float* z = g_zc + (size_t)b * (8192 * 384) + (size_t)d * 24576;

    float v[8];
#pragma unroll
    for (int k = 0; k < 8; k++) v[k] = z[16384 + tid + k * 1024];

    for (int it = 0; it < 2; it++) {
        const float* h = g_hT + (size_t)((b * 2 + it) * 128 + d) * 8192;

#pragma unroll
        for (int jj = 0; jj < 4; jj++) {
            int j = tid + jj * 1024;
            float2 x0 = make_float2(v[jj],     h[j]);
            float2 x1 = make_float2(v[jj + 4], h[j + 4096]);
            float2 W1 = g_tw[j];
            float2 W2 = make_float2(W1.y, -W1.x);
            float2 W3 = cmul(W1, W1);
            float2 t02m = cmul(x0, W1);
            float2 t13m = cmul(x1, W2);
            sh[PH(j)]         = cadd(x0, x1);
            sh[PH(j + 4096)]  = cmul(csub(x0, x1), W3);
            sh[PH(j + 8192)]  = cadd(t02m, t13m);
            sh[PH(j + 12288)] = cmul(csub(t02m, t13m), W3);
        }
        __syncthreads();

#pragma unroll
        for (int lg = 11; lg >= 1; lg -= 2) {
            int half = 1 << (lg - 1);
#pragma unroll
            for (int jj = 0; jj < 4; jj++) {
                int j   = tid + jj * 1024;
                int off = j & (half - 1);
                int i   = ((j >> (lg - 1)) << (lg + 1)) + off;
                float2 x0 = sh[PH(i)];
                float2 x1 = sh[PH(i + half)];
                float2 x2 = sh[PH(i + 2 * half)];
                float2 x3 = sh[PH(i + 3 * half)];
                float2 W1 = g_tw[off << (13 - lg)];
                float2 W2 = make_float2(W1.y, -W1.x);
                float2 W3 = cmul(W1, W1);
                float2 t02p = cadd(x0, x2);
                float2 t02m = cmul(csub(x0, x2), W1);
                float2 t13p = cadd(x1, x3);
                float2 t13m = cmul(csub(x1, x3), W2);
                sh[PH(i)]            = cadd(t02p, t13p);
                sh[PH(i + half)]     = cmul(csub(t02p, t13p), W3);
                sh[PH(i + 2 * half)] = cadd(t02m, t13m);
                sh[PH(i + 3 * half)] = cmul(csub(t02m, t13m), W3);
            }
            __syncthreads();
        }

        float2 ur[16];
#pragma unroll
        for (int k = 0; k < 16; k++) {
            int p  = tid + k * 1024;
            int kk = __brev(p) >> 18;
            int k2 = (16384 - kk) & 16383;
            int p2 = __brev(k2) >> 18;
            float2 P = sh[PH(p)], Q = sh[PH(p2)];
            float vx = 0.5f * (P.x + Q.x), vy = 0.5f * (P.y - Q.y);
            float hx = 0.5f * (P.y + Q.y), hy = 0.5f * (Q.x - P.x);
            ur[k] = make_float2(vx * hx - vy * hy, vx * hy + vy * hx);
        }
        __syncthreads();
#pragma unroll
        for (int k = 0; k < 16; k++) sh[PH(tid + k * 1024)] = ur[k];
        __syncthreads();

#pragma unroll
        for (int lg = 0; lg <= 10; lg += 2) {
            int len = 1 << lg;
#pragma unroll
            for (int jj = 0; jj < 4; jj++) {
                int j   = tid + jj * 1024;
                int off = j & (len - 1);
                int i   = ((j >> lg) << (lg + 2)) + off;
                float2 x0 = sh[PH(i)];
                float2 x1 = sh[PH(i + len)];
                float2 x2 = sh[PH(i + 2 * len)];
                float2 x3 = sh[PH(i + 3 * len)];
                float2 w   = g_tw[off << (12 - lg)];
                float2 cw2 = make_float2(w.x, -w.y);
                float2 cw1 = cmul(cw2, cw2);
                float2 cw3 = make_float2(-cw2.y, cw2.x);
                float2 b1 = cmul(x1, cw1);
                float2 b3 = cmul(x3, cw1);
                float2 u0 = cadd(x0, b1), u1 = csub(x0, b1);
                float2 u2 = cadd(x2, b3), u3 = csub(x2, b3);
                float2 c2 = cmul(u2, cw2);
                float2 c3 = cmul(u3, cw3);
                sh[PH(i)]           = cadd(u0, c2);
                sh[PH(i + 2 * len)] = csub(u0, c2);
                sh[PH(i + len)]     = cadd(u1, c3);
                sh[PH(i + 3 * len)] = csub(u1, c3);
            }
            __syncthreads();
        }

        const float* zn = z + it * 8192;
        float Bn = Bp[it * 128 + d];
#pragma unroll
        for (int jj = 0; jj < 4; jj++) {
            int j = tid + jj * 1024;
            float2 x0 = sh[PH(j)];
            float2 x1 = sh[PH(j + 4096)];
            float2 x2 = sh[PH(j + 8192)];
            float2 x3 = sh[PH(j + 12288)];
            float2 w   = g_tw[j];
            float2 cw2 = make_float2(w.x, -w.y);
            float2 cw1 = cmul(cw2, cw2);
            float2 cw3 = make_float2(-cw2.y, cw2.x);
            float2 b1 = cmul(x1, cw1);
            float2 b3 = cmul(x3, cw1);
            float2 u0 = cadd(x0, b1), u1 = csub(x0, b1);
            float2 u2 = cadd(x2, b3), u3 = csub(x2, b3);
            float y0x = u0.x + (u2.x * cw2.x - u2.y * cw2.y);
            float y1x = u1.x + (u3.x * cw3.x - u3.y * cw3.y);
            v[jj]     = zn[j]        * (y0x * SCALE_U + Bn * v[jj]);
            v[jj + 4] = zn[j + 4096] * (y1x * SCALE_U + Bn * v[jj + 4]);
        }
        __syncthreads();
    }
    float* vo = g_vT + (size_t)(b * 128 + d) * 8192;
#pragma unroll
    for (int k = 0; k < 8; k++) vo[tid + k * 1024] = v[k];
}

extern "C" void kernel_launch(void* const* d_in, const int* in_sizes, int n_in,
                              void* d_out, int out_size) {
    const float* emb = (const float*)d_in[0];
    const float* Wp  = (const float*)d_in[1];
    const float* cw  = (const float*)d_in[2];
    const float* cb  = (const float*)d_in[3];
    const float* W1  = (const float*)d_in[4];
    const float* b1  = (const float*)d_in[5];
    const float* lng = (const float*)d_in[6];
    const float* lnb = (const float*)d_in[7];
    const float* W2  = (const float*)d_in[8];
    const float* b2  = (const float*)d_in[9];
    const float* ffs = (const float*)d_in[10];
    const float* op  = (const float*)d_in[11];
    const float* Bp  = (const float*)d_in[12];
    const int*   pos = (const int*)d_in[13];
    float* out = (float*)d_out;

    cudaFuncSetAttribute(k_fftrec, cudaFuncAttributeMaxDynamicSharedMemorySize, 131072);

    k_twiddle<<<32, 256>>>();
    k_sgemm<0><<<dim3(256, 3), 256>>>(emb, Wp, nullptr, nullptr, nullptr, nullptr);
    k_conv<<<12288, 256>>>(cw, cb);
    k_rope<<<8192, 256>>>(emb, pos);
    k_sgemm<1><<<dim3(256, 1), 256>>>(nullptr, W1, b1, lng, lnb, nullptr);
    k_sgemm<2><<<dim3(256, 2), 256>>>(nullptr, W2, b2, ffs, nullptr, nullptr);
    k_fftrec<<<512, 1024, 131072>>>(Bp);
    k_sgemm<3><<<dim3(256, 1), 256>>>(nullptr, op, nullptr, nullptr, nullptr, out);
}